// round 1
// baseline (speedup 1.0000x reference)
#include <cuda_runtime.h>
#include <cstdint>

// Problem constants
#define BB      2
#define TT      2048
#define DMODEL  1024
#define DINNER  2048
#define DSTATE  32
#define DTRANK  64
#define MM      (BB * TT)            // 4096
#define NSPLIT  16                   // split-K for x-proj GEMM

// ---------------- scratch (device globals; no cudaMalloc allowed) ----------
__device__ float g_xn  [MM * DMODEL];          // layernorm out         16.8MB
__device__ float g_xz  [MM * 2 * DINNER];      // in-proj out           67MB
__device__ float g_xdbl[MM * 128];             // x-proj out            2MB
__device__ float g_part[NSPLIT * MM * 128];    // split-K partials      33.5MB
__device__ float g_dt  [MM * DINNER];          // dt (m,e)              33.5MB
__device__ float g_dtT [MM * DINNER];          // dt (b,e,t)            33.5MB
__device__ float g_xT  [MM * DINNER];          // x_ssm (b,e,t)         33.5MB
__device__ float g_y   [MM * DINNER];          // scan out y (m,e)      33.5MB

// ---------------- LayerNorm: one block per row of 1024 ---------------------
__global__ void ln_kernel(const float* __restrict__ x, const float* __restrict__ g,
                          const float* __restrict__ b, float* __restrict__ xn)
{
    int row = blockIdx.x;
    int tid = threadIdx.x;                         // 256 threads, 4 floats each
    const float4 v = ((const float4*)(x + (size_t)row * DMODEL))[tid];
    float s  = v.x + v.y + v.z + v.w;
    float s2 = v.x*v.x + v.y*v.y + v.z*v.z + v.w*v.w;
    #pragma unroll
    for (int o = 16; o; o >>= 1) {
        s  += __shfl_xor_sync(0xffffffffu, s,  o);
        s2 += __shfl_xor_sync(0xffffffffu, s2, o);
    }
    __shared__ float sm[2][8];
    int w = tid >> 5, l = tid & 31;
    if (l == 0) { sm[0][w] = s; sm[1][w] = s2; }
    __syncthreads();
    if (w == 0) {
        s  = (l < 8) ? sm[0][l] : 0.f;
        s2 = (l < 8) ? sm[1][l] : 0.f;
        #pragma unroll
        for (int o = 4; o; o >>= 1) {
            s  += __shfl_xor_sync(0xffffffffu, s,  o);
            s2 += __shfl_xor_sync(0xffffffffu, s2, o);
        }
        if (l == 0) { sm[0][0] = s; sm[1][0] = s2; }
    }
    __syncthreads();
    float mu  = sm[0][0] * (1.f / DMODEL);
    float var = sm[1][0] * (1.f / DMODEL) - mu * mu;
    float rs  = rsqrtf(var + 1e-5f);
    const float4 gv = ((const float4*)g)[tid];
    const float4 bv = ((const float4*)b)[tid];
    float4 o;
    o.x = (v.x - mu) * rs * gv.x + bv.x;
    o.y = (v.y - mu) * rs * gv.y + bv.y;
    o.z = (v.z - mu) * rs * gv.z + bv.z;
    o.w = (v.w - mu) * rs * gv.w + bv.w;
    ((float4*)(xn + (size_t)row * DMODEL))[tid] = o;
}

// ---------------- SGEMM: C[M,N] = A[M,K] * B[N,K]^T  (both K-contiguous) ---
// 128x128 tile, BK=8, 256 threads, 8x8 per thread, double-buffered smem.
// EPI: 0 = plain store, 1 = softplus(acc + bias[n]), 2 = acc + resid[m*ldr+n]
// Split-K via blockIdx.z: A/B advance by z*K columns, C by z*zstride elems.
template<int EPI>
__global__ __launch_bounds__(256, 2)
void sgemm_nt(const float* __restrict__ A, int lda,
              const float* __restrict__ B, int ldb,
              float* __restrict__ C, int ldc,
              int M, int N, int K,
              const float* __restrict__ bias,
              const float* __restrict__ resid, int ldr,
              int zstride)
{
    const int BM = 128, BN = 128, BK = 8, PAD = 132;
    __shared__ float As[2][BK][PAD];
    __shared__ float Bs[2][BK][PAD];

    int koff = blockIdx.z * K;
    A += koff; B += koff;
    C += (size_t)blockIdx.z * zstride;

    int tid = threadIdx.x;
    int tx = tid & 15, ty = tid >> 4;
    int m0 = blockIdx.y * BM, n0 = blockIdx.x * BN;

    int lrow = tid >> 1;
    int lcol = (tid & 1) * 4;
    const float* Ag = A + (size_t)(m0 + lrow) * lda + lcol;
    const float* Bg = B + (size_t)(n0 + lrow) * ldb + lcol;

    int nt = K / BK;
    float4 aReg = *(const float4*)Ag;
    float4 bReg = *(const float4*)Bg;
    As[0][lcol + 0][lrow] = aReg.x; As[0][lcol + 1][lrow] = aReg.y;
    As[0][lcol + 2][lrow] = aReg.z; As[0][lcol + 3][lrow] = aReg.w;
    Bs[0][lcol + 0][lrow] = bReg.x; Bs[0][lcol + 1][lrow] = bReg.y;
    Bs[0][lcol + 2][lrow] = bReg.z; Bs[0][lcol + 3][lrow] = bReg.w;
    __syncthreads();

    float acc[8][8] = {};
    float af[8], bf[8];
    int cur = 0;
    for (int kt = 0; kt < nt; kt++) {
        bool more = (kt + 1 < nt);
        if (more) {
            aReg = *(const float4*)(Ag + (kt + 1) * BK);
            bReg = *(const float4*)(Bg + (kt + 1) * BK);
        }
        #pragma unroll
        for (int kk = 0; kk < BK; kk++) {
            *(float4*)(af)     = *(const float4*)&As[cur][kk][ty * 4];
            *(float4*)(af + 4) = *(const float4*)&As[cur][kk][64 + ty * 4];
            *(float4*)(bf)     = *(const float4*)&Bs[cur][kk][tx * 4];
            *(float4*)(bf + 4) = *(const float4*)&Bs[cur][kk][64 + tx * 4];
            #pragma unroll
            for (int i = 0; i < 8; i++)
                #pragma unroll
                for (int j = 0; j < 8; j++)
                    acc[i][j] = fmaf(af[i], bf[j], acc[i][j]);
        }
        if (more) {
            int nxt = cur ^ 1;
            As[nxt][lcol + 0][lrow] = aReg.x; As[nxt][lcol + 1][lrow] = aReg.y;
            As[nxt][lcol + 2][lrow] = aReg.z; As[nxt][lcol + 3][lrow] = aReg.w;
            Bs[nxt][lcol + 0][lrow] = bReg.x; Bs[nxt][lcol + 1][lrow] = bReg.y;
            Bs[nxt][lcol + 2][lrow] = bReg.z; Bs[nxt][lcol + 3][lrow] = bReg.w;
            __syncthreads();
            cur = nxt;
        }
    }

    #pragma unroll
    for (int i = 0; i < 8; i++) {
        int m = m0 + ((i < 4) ? (ty * 4 + i) : (64 + ty * 4 + i - 4));
        #pragma unroll
        for (int jj = 0; jj < 2; jj++) {
            int n = n0 + jj * 64 + tx * 4;
            float4 v;
            v.x = acc[i][jj * 4 + 0];
            v.y = acc[i][jj * 4 + 1];
            v.z = acc[i][jj * 4 + 2];
            v.w = acc[i][jj * 4 + 3];
            if (EPI == 1) {
                const float4 bb = *(const float4*)&bias[n];
                v.x = log1pf(__expf(v.x + bb.x));
                v.y = log1pf(__expf(v.y + bb.y));
                v.z = log1pf(__expf(v.z + bb.z));
                v.w = log1pf(__expf(v.w + bb.w));
            } else if (EPI == 2) {
                const float4 rr = *(const float4*)&resid[(size_t)m * ldr + n];
                v.x += rr.x; v.y += rr.y; v.z += rr.z; v.w += rr.w;
            }
            *(float4*)&C[(size_t)m * ldc + n] = v;
        }
    }
}

// ---------------- split-K reduce ------------------------------------------
__global__ void reduce_splitk(const float* __restrict__ part, float* __restrict__ out, int n)
{
    int i = blockIdx.x * blockDim.x + threadIdx.x;
    if (i >= n) return;
    float s = 0.f;
    #pragma unroll
    for (int z = 0; z < NSPLIT; z++) s += part[(size_t)z * n + i];
    out[i] = s;
}

// ---------------- transpose dt and x_ssm to (b, e, t) ----------------------
__global__ void transpose_dx(const float* __restrict__ dt, const float* __restrict__ xz,
                             float* __restrict__ dtT, float* __restrict__ xT)
{
    __shared__ float t1[32][33], t2[32][33];
    int b = blockIdx.z;
    int t0 = blockIdx.x * 32, e0 = blockIdx.y * 32;
    int x = threadIdx.x, y = threadIdx.y;
    #pragma unroll
    for (int j = 0; j < 32; j += 8) {
        size_t r = (size_t)(b * TT + t0 + y + j);
        t1[y + j][x] = dt[r * DINNER + e0 + x];
        t2[y + j][x] = xz[r * (2 * DINNER) + e0 + x];
    }
    __syncthreads();
    #pragma unroll
    for (int j = 0; j < 32; j += 8) {
        size_t r = (size_t)(b * DINNER + e0 + y + j);
        dtT[r * TT + t0 + x] = t1[x][y + j];
        xT [r * TT + t0 + x] = t2[x][y + j];
    }
}

// ---------------- selective scan: 1 warp per (b,e), lane = state n ---------
__global__ __launch_bounds__(256)
void scan_kernel(const float* __restrict__ dtT, const float* __restrict__ xT,
                 const float* __restrict__ xdbl,
                 const float* __restrict__ A_log_real, const float* __restrict__ A_imag,
                 const float* __restrict__ D_param, float* __restrict__ y)
{
    const int CH = 64;
    __shared__ float Bs[CH][32], Cs[CH][32], dts[8][CH], xs[8][CH];
    int b = blockIdx.y;
    int w = threadIdx.x >> 5, lane = threadIdx.x & 31;
    int e = blockIdx.x * 8 + w;

    float Ar = -__expf(A_log_real[e * DSTATE + lane]);
    float Ai = A_imag[e * DSTATE + lane];
    float Dp = D_param[e];
    float hr = 0.f, hi = 0.f;

    const float* dtc = dtT + (size_t)(b * DINNER + e) * TT;
    const float* xc  = xT  + (size_t)(b * DINNER + e) * TT;
    const float* bc  = xdbl + (size_t)b * TT * 128;

    for (int tc = 0; tc < TT; tc += CH) {
        for (int i = threadIdx.x; i < CH * 32; i += 256) {
            int tl = i >> 5, n = i & 31;
            Bs[tl][n] = bc[(tc + tl) * 128 + DTRANK + n];
            Cs[tl][n] = bc[(tc + tl) * 128 + DTRANK + DSTATE + n];
        }
        for (int j = lane; j < CH; j += 32) {
            dts[w][j] = dtc[tc + j];
            xs[w][j]  = xc[tc + j];
        }
        __syncthreads();
        #pragma unroll 4
        for (int j = 0; j < CH; j++) {
            float dtv = dts[w][j];
            float xv  = xs[w][j];
            float Bv  = Bs[j][lane];
            float Cv  = Cs[j][lane];
            float sc  = __expf(Ar * dtv);
            float sn, cs;
            __sincosf(Ai * dtv, &sn, &cs);
            float dAr = sc * cs, dAi = sc * sn;
            float dBx = dtv * xv * Bv;
            float hr2 = fmaf(dAr, hr, fmaf(-dAi, hi, dBx));
            float hi2 = fmaf(dAr, hi, dAi * hr);
            hr = hr2; hi = hi2;
            float p = hr2 * Cv;
            #pragma unroll
            for (int o = 16; o; o >>= 1) p += __shfl_xor_sync(0xffffffffu, p, o);
            if (lane == 0)
                y[(size_t)(b * TT + tc + j) * DINNER + e] = fmaf(Dp, xv, p);
        }
        __syncthreads();
    }
}

// ---------------- y *= silu(z) ---------------------------------------------
__global__ void yz_kernel(float* __restrict__ y, const float* __restrict__ xz)
{
    int i = blockIdx.x * blockDim.x + threadIdx.x;   // over MM*DINNER/4
    int m = i >> 9;
    int c = (i & 511) << 2;
    float4 yv = *(float4*)(y + (size_t)m * DINNER + c);
    const float4 zv = *(const float4*)(xz + (size_t)m * (2 * DINNER) + DINNER + c);
    yv.x *= zv.x / (1.f + __expf(-zv.x));
    yv.y *= zv.y / (1.f + __expf(-zv.y));
    yv.z *= zv.z / (1.f + __expf(-zv.z));
    yv.w *= zv.w / (1.f + __expf(-zv.w));
    *(float4*)(y + (size_t)m * DINNER + c) = yv;
}

// ---------------- host ------------------------------------------------------
static float* symaddr(const void* sym)
{
    void* p = nullptr;
    cudaGetSymbolAddress(&p, sym);
    return (float*)p;
}

extern "C" void kernel_launch(void* const* d_in, const int* in_sizes, int n_in,
                              void* d_out, int out_size)
{
    const float* x          = (const float*)d_in[0];
    const float* W_in       = (const float*)d_in[1];
    const float* W_x        = (const float*)d_in[2];
    const float* W_dt       = (const float*)d_in[3];
    const float* b_dt       = (const float*)d_in[4];
    const float* A_log_real = (const float*)d_in[5];
    const float* A_imag     = (const float*)d_in[6];
    const float* D_param    = (const float*)d_in[7];
    const float* W_out      = (const float*)d_in[8];
    const float* ln_g       = (const float*)d_in[9];
    const float* ln_b       = (const float*)d_in[10];
    float* out = (float*)d_out;

    float* p_xn   = symaddr(g_xn);
    float* p_xz   = symaddr(g_xz);
    float* p_xdbl = symaddr(g_xdbl);
    float* p_part = symaddr(g_part);
    float* p_dt   = symaddr(g_dt);
    float* p_dtT  = symaddr(g_dtT);
    float* p_xT   = symaddr(g_xT);
    float* p_y    = symaddr(g_y);

    // 1. LayerNorm
    ln_kernel<<<MM, 256>>>(x, ln_g, ln_b, p_xn);

    // 2. in-proj: xz = xn @ W_in^T   (M=4096, N=4096, K=1024)
    sgemm_nt<0><<<dim3(4096 / 128, MM / 128, 1), 256>>>(
        p_xn, DMODEL, W_in, DMODEL, p_xz, 2 * DINNER,
        MM, 2 * DINNER, DMODEL, nullptr, nullptr, 0, 0);

    // 3. x-proj: x_dbl = x_ssm @ W_x^T  (M=4096, N=128, K=2048) split-K x16
    sgemm_nt<0><<<dim3(1, MM / 128, NSPLIT), 256>>>(
        p_xz, 2 * DINNER, W_x, DINNER, p_part, 128,
        MM, 128, DINNER / NSPLIT, nullptr, nullptr, 0, MM * 128);
    reduce_splitk<<<(MM * 128 + 255) / 256, 256>>>(p_part, p_xdbl, MM * 128);

    // 4. dt-proj + softplus: dt = softplus(dt_low @ W_dt^T + b_dt)
    sgemm_nt<1><<<dim3(DINNER / 128, MM / 128, 1), 256>>>(
        p_xdbl, 128, W_dt, DTRANK, p_dt, DINNER,
        MM, DINNER, DTRANK, b_dt, nullptr, 0, 0);

    // 5. transpose dt, x_ssm to (b, e, t)
    transpose_dx<<<dim3(TT / 32, DINNER / 32, BB), dim3(32, 8)>>>(p_dt, p_xz, p_dtT, p_xT);

    // 6. selective scan
    scan_kernel<<<dim3(DINNER / 8, BB), 256>>>(p_dtT, p_xT, p_xdbl,
                                               A_log_real, A_imag, D_param, p_y);

    // 7. y *= silu(z)
    yz_kernel<<<(MM * DINNER / 4) / 256, 256>>>(p_y, p_xz);

    // 8. out-proj + residual: out = x + (y) @ W_out^T  (M=4096, N=1024, K=2048)
    sgemm_nt<2><<<dim3(DMODEL / 128, MM / 128, 1), 256>>>(
        p_y, DINNER, W_out, DINNER, out, DMODEL,
        MM, DMODEL, DINNER, nullptr, x, DMODEL, 0);
}

// round 3
// speedup vs baseline: 1.5584x; 1.5584x over previous
#include <cuda_runtime.h>
#include <cstdint>

// Problem constants
#define BB      2
#define TT      2048
#define DMODEL  1024
#define DINNER  2048
#define DSTATE  32
#define DTRANK  64
#define MM      (BB * TT)            // 4096
#define NSPLIT  8                    // split-K for x-proj GEMM

// ---------------- scratch (device globals; no cudaMalloc allowed) ----------
__device__ float g_xn  [MM * DMODEL];
__device__ float g_xz  [MM * 2 * DINNER];
__device__ float g_xdbl[MM * 128];
__device__ float g_part[NSPLIT * MM * 128];
__device__ float g_dt  [MM * DINNER];
__device__ float g_dtT [MM * DINNER];
__device__ float g_xT  [MM * DINNER];
__device__ float g_y   [MM * DINNER];

// ---------------- helpers ---------------------------------------------------
__device__ __forceinline__ float f2tf(float x)
{
    uint32_t r;
    asm("cvt.rna.tf32.f32 %0, %1;" : "=r"(r) : "f"(x));
    return __uint_as_float(r);
}

__device__ __forceinline__ void mma1688(float* d, const uint32_t* a, const uint32_t* b)
{
    asm volatile(
        "mma.sync.aligned.m16n8k8.row.col.f32.tf32.tf32.f32 "
        "{%0,%1,%2,%3}, {%4,%5,%6,%7}, {%8,%9}, {%0,%1,%2,%3};"
        : "+f"(d[0]), "+f"(d[1]), "+f"(d[2]), "+f"(d[3])
        : "r"(a[0]), "r"(a[1]), "r"(a[2]), "r"(a[3]), "r"(b[0]), "r"(b[1]));
}

// ============ tf32 tensor-core GEMM: C[M,N] = A[M,K] * B[N,K]^T =============
// 128x128 CTA tile, BK=16, 256 threads (8 warps, 2x4 warp grid, 64x32/warp).
// Smem k-major [BK][136] (conflict-free frag loads). Double-buffered.
// EPI: 0 plain, 1 softplus(acc + bias[n]), 2 acc + resid[m*ldr+n]
// Split-K via blockIdx.z: A/B advance by z*K cols, C by z*zstride elems.
template<int EPI>
__global__ __launch_bounds__(256, 2)
void tmma(const float* __restrict__ A, int lda,
          const float* __restrict__ B, int ldb,
          float* __restrict__ C, int ldc, int K,
          const float* __restrict__ bias,
          const float* __restrict__ resid, int ldr,
          int zstride)
{
    const int BK = 16, STR = 136;
    __shared__ float As[2][BK][STR];
    __shared__ float Bs[2][BK][STR];

    int koff = blockIdx.z * K;
    A += koff; B += koff;
    C += (size_t)blockIdx.z * zstride;

    int tid = threadIdx.x;
    int wid = tid >> 5, lane = tid & 31;
    int warp_m = wid >> 2, warp_n = wid & 3;
    int m0 = blockIdx.y * 128, n0 = blockIdx.x * 128;

    // loader: thread covers p = tid and p = tid + 256; row = p>>2, kq = p&3
    int ar0 = tid >> 2,  ak0 = (tid & 3) * 4;
    int ar1 = ar0 + 64;                       // (tid+256)>>2
    const float* Ag0 = A + (size_t)(m0 + ar0) * lda + ak0;
    const float* Ag1 = A + (size_t)(m0 + ar1) * lda + ak0;
    const float* Bg0 = B + (size_t)(n0 + ar0) * ldb + ak0;
    const float* Bg1 = B + (size_t)(n0 + ar1) * ldb + ak0;

    int NK = K >> 4;

    float4 a0 = *(const float4*)Ag0;
    float4 a1 = *(const float4*)Ag1;
    float4 b0 = *(const float4*)Bg0;
    float4 b1 = *(const float4*)Bg1;
    As[0][ak0+0][ar0] = f2tf(a0.x); As[0][ak0+1][ar0] = f2tf(a0.y);
    As[0][ak0+2][ar0] = f2tf(a0.z); As[0][ak0+3][ar0] = f2tf(a0.w);
    As[0][ak0+0][ar1] = f2tf(a1.x); As[0][ak0+1][ar1] = f2tf(a1.y);
    As[0][ak0+2][ar1] = f2tf(a1.z); As[0][ak0+3][ar1] = f2tf(a1.w);
    Bs[0][ak0+0][ar0] = f2tf(b0.x); Bs[0][ak0+1][ar0] = f2tf(b0.y);
    Bs[0][ak0+2][ar0] = f2tf(b0.z); Bs[0][ak0+3][ar0] = f2tf(b0.w);
    Bs[0][ak0+0][ar1] = f2tf(b1.x); Bs[0][ak0+1][ar1] = f2tf(b1.y);
    Bs[0][ak0+2][ar1] = f2tf(b1.z); Bs[0][ak0+3][ar1] = f2tf(b1.w);
    __syncthreads();

    float acc[4][4][4] = {};
    int r4 = lane >> 2, c4 = lane & 3;
    int cur = 0;

    for (int kt = 0; kt < NK; kt++) {
        bool more = (kt + 1 < NK);
        if (more) {
            a0 = *(const float4*)(Ag0 + (kt + 1) * BK);
            a1 = *(const float4*)(Ag1 + (kt + 1) * BK);
            b0 = *(const float4*)(Bg0 + (kt + 1) * BK);
            b1 = *(const float4*)(Bg1 + (kt + 1) * BK);
        }
        #pragma unroll
        for (int ks = 0; ks < 16; ks += 8) {
            uint32_t af[4][4], bf[4][2];
            #pragma unroll
            for (int mi = 0; mi < 4; mi++) {
                int r = warp_m * 64 + mi * 16 + r4;
                int c = ks + c4;
                af[mi][0] = __float_as_uint(As[cur][c    ][r    ]);
                af[mi][1] = __float_as_uint(As[cur][c    ][r + 8]);
                af[mi][2] = __float_as_uint(As[cur][c + 4][r    ]);
                af[mi][3] = __float_as_uint(As[cur][c + 4][r + 8]);
            }
            #pragma unroll
            for (int nj = 0; nj < 4; nj++) {
                int n = warp_n * 32 + nj * 8 + r4;
                bf[nj][0] = __float_as_uint(Bs[cur][ks + c4    ][n]);
                bf[nj][1] = __float_as_uint(Bs[cur][ks + c4 + 4][n]);
            }
            #pragma unroll
            for (int mi = 0; mi < 4; mi++)
                #pragma unroll
                for (int nj = 0; nj < 4; nj++)
                    mma1688(acc[mi][nj], af[mi], bf[nj]);
        }
        if (more) {
            int nxt = cur ^ 1;
            As[nxt][ak0+0][ar0] = f2tf(a0.x); As[nxt][ak0+1][ar0] = f2tf(a0.y);
            As[nxt][ak0+2][ar0] = f2tf(a0.z); As[nxt][ak0+3][ar0] = f2tf(a0.w);
            As[nxt][ak0+0][ar1] = f2tf(a1.x); As[nxt][ak0+1][ar1] = f2tf(a1.y);
            As[nxt][ak0+2][ar1] = f2tf(a1.z); As[nxt][ak0+3][ar1] = f2tf(a1.w);
            Bs[nxt][ak0+0][ar0] = f2tf(b0.x); Bs[nxt][ak0+1][ar0] = f2tf(b0.y);
            Bs[nxt][ak0+2][ar0] = f2tf(b0.z); Bs[nxt][ak0+3][ar0] = f2tf(b0.w);
            Bs[nxt][ak0+0][ar1] = f2tf(b1.x); Bs[nxt][ak0+1][ar1] = f2tf(b1.y);
            Bs[nxt][ak0+2][ar1] = f2tf(b1.z); Bs[nxt][ak0+3][ar1] = f2tf(b1.w);
            __syncthreads();
            cur = nxt;
        }
    }

    // Epilogue: c0,c1 at (row, 2*c4), c2,c3 at (row+8, 2*c4)
    #pragma unroll
    for (int mi = 0; mi < 4; mi++) {
        #pragma unroll
        for (int nj = 0; nj < 4; nj++) {
            int m = m0 + warp_m * 64 + mi * 16 + r4;
            int n = n0 + warp_n * 32 + nj * 8 + c4 * 2;
            #pragma unroll
            for (int h = 0; h < 2; h++) {
                int mm = m + h * 8;
                float vx = acc[mi][nj][h * 2 + 0];
                float vy = acc[mi][nj][h * 2 + 1];
                if (EPI == 1) {
                    vx = log1pf(__expf(vx + bias[n]));
                    vy = log1pf(__expf(vy + bias[n + 1]));
                } else if (EPI == 2) {
                    const float2 rv = *(const float2*)&resid[(size_t)mm * ldr + n];
                    vx += rv.x; vy += rv.y;
                }
                float2 o = { vx, vy };
                *(float2*)&C[(size_t)mm * ldc + n] = o;
            }
        }
    }
}

// ---------------- split-K reduce -------------------------------------------
__global__ void reduce_splitk(const float* __restrict__ part, float* __restrict__ out, int n)
{
    int i = blockIdx.x * blockDim.x + threadIdx.x;
    if (i >= n) return;
    float s = 0.f;
    #pragma unroll
    for (int z = 0; z < NSPLIT; z++) s += part[(size_t)z * n + i];
    out[i] = s;
}

// ---------------- LayerNorm: one block per row of 1024 ---------------------
__global__ void ln_kernel(const float* __restrict__ x, const float* __restrict__ g,
                          const float* __restrict__ b, float* __restrict__ xn)
{
    int row = blockIdx.x;
    int tid = threadIdx.x;
    const float4 v = ((const float4*)(x + (size_t)row * DMODEL))[tid];
    float s  = v.x + v.y + v.z + v.w;
    float s2 = v.x*v.x + v.y*v.y + v.z*v.z + v.w*v.w;
    #pragma unroll
    for (int o = 16; o; o >>= 1) {
        s  += __shfl_xor_sync(0xffffffffu, s,  o);
        s2 += __shfl_xor_sync(0xffffffffu, s2, o);
    }
    __shared__ float sm[2][8];
    int w = tid >> 5, l = tid & 31;
    if (l == 0) { sm[0][w] = s; sm[1][w] = s2; }
    __syncthreads();
    if (w == 0) {
        s  = (l < 8) ? sm[0][l] : 0.f;
        s2 = (l < 8) ? sm[1][l] : 0.f;
        #pragma unroll
        for (int o = 4; o; o >>= 1) {
            s  += __shfl_xor_sync(0xffffffffu, s,  o);
            s2 += __shfl_xor_sync(0xffffffffu, s2, o);
        }
        if (l == 0) { sm[0][0] = s; sm[1][0] = s2; }
    }
    __syncthreads();
    float mu  = sm[0][0] * (1.f / DMODEL);
    float var = sm[1][0] * (1.f / DMODEL) - mu * mu;
    float rs  = rsqrtf(var + 1e-5f);
    const float4 gv = ((const float4*)g)[tid];
    const float4 bv = ((const float4*)b)[tid];
    float4 o;
    o.x = (v.x - mu) * rs * gv.x + bv.x;
    o.y = (v.y - mu) * rs * gv.y + bv.y;
    o.z = (v.z - mu) * rs * gv.z + bv.z;
    o.w = (v.w - mu) * rs * gv.w + bv.w;
    ((float4*)(xn + (size_t)row * DMODEL))[tid] = o;
}

// ---------------- transpose dt and x_ssm to (b, e, t) ----------------------
__global__ void transpose_dx(const float* __restrict__ dt, const float* __restrict__ xz,
                             float* __restrict__ dtT, float* __restrict__ xT)
{
    __shared__ float t1[32][33], t2[32][33];
    int b = blockIdx.z;
    int t0 = blockIdx.x * 32, e0 = blockIdx.y * 32;
    int x = threadIdx.x, y = threadIdx.y;
    #pragma unroll
    for (int j = 0; j < 32; j += 8) {
        size_t r = (size_t)(b * TT + t0 + y + j);
        t1[y + j][x] = dt[r * DINNER + e0 + x];
        t2[y + j][x] = xz[r * (2 * DINNER) + e0 + x];
    }
    __syncthreads();
    #pragma unroll
    for (int j = 0; j < 32; j += 8) {
        size_t r = (size_t)(b * DINNER + e0 + y + j);
        dtT[r * TT + t0 + x] = t1[x][y + j];
        xT [r * TT + t0 + x] = t2[x][y + j];
    }
}

// ---------------- selective scan: 1 warp per (b,e), lane = state n ---------
__global__ __launch_bounds__(256)
void scan_kernel(const float* __restrict__ dtT, const float* __restrict__ xT,
                 const float* __restrict__ xdbl,
                 const float* __restrict__ A_log_real, const float* __restrict__ A_imag,
                 const float* __restrict__ D_param, float* __restrict__ y)
{
    const int CH = 64;
    __shared__ float Bs[CH][32], Cs[CH][32], dts[8][CH], xs[8][CH];
    int b = blockIdx.y;
    int w = threadIdx.x >> 5, lane = threadIdx.x & 31;
    int e = blockIdx.x * 8 + w;

    float Ar = -__expf(A_log_real[e * DSTATE + lane]);
    float Ai = A_imag[e * DSTATE + lane];
    float Dp = D_param[e];
    float hr = 0.f, hi = 0.f;

    const float* dtc = dtT + (size_t)(b * DINNER + e) * TT;
    const float* xc  = xT  + (size_t)(b * DINNER + e) * TT;
    const float* bc  = xdbl + (size_t)b * TT * 128;

    for (int tc = 0; tc < TT; tc += CH) {
        for (int i = threadIdx.x; i < CH * 32; i += 256) {
            int tl = i >> 5, n = i & 31;
            Bs[tl][n] = bc[(tc + tl) * 128 + DTRANK + n];
            Cs[tl][n] = bc[(tc + tl) * 128 + DTRANK + DSTATE + n];
        }
        for (int j = lane; j < CH; j += 32) {
            dts[w][j] = dtc[tc + j];
            xs[w][j]  = xc[tc + j];
        }
        __syncthreads();
        #pragma unroll 4
        for (int j = 0; j < CH; j++) {
            float dtv = dts[w][j];
            float xv  = xs[w][j];
            float Bv  = Bs[j][lane];
            float Cv  = Cs[j][lane];
            float sc  = __expf(Ar * dtv);
            float sn, cs;
            __sincosf(Ai * dtv, &sn, &cs);
            float dAr = sc * cs, dAi = sc * sn;
            float dBx = dtv * xv * Bv;
            float hr2 = fmaf(dAr, hr, fmaf(-dAi, hi, dBx));
            float hi2 = fmaf(dAr, hi, dAi * hr);
            hr = hr2; hi = hi2;
            float p = hr2 * Cv;
            #pragma unroll
            for (int o = 16; o; o >>= 1) p += __shfl_xor_sync(0xffffffffu, p, o);
            if (lane == 0)
                y[(size_t)(b * TT + tc + j) * DINNER + e] = fmaf(Dp, xv, p);
        }
        __syncthreads();
    }
}

// ---------------- y *= silu(z) ---------------------------------------------
__global__ void yz_kernel(float* __restrict__ y, const float* __restrict__ xz)
{
    int i = blockIdx.x * blockDim.x + threadIdx.x;
    int m = i >> 9;
    int c = (i & 511) << 2;
    float4 yv = *(float4*)(y + (size_t)m * DINNER + c);
    const float4 zv = *(const float4*)(xz + (size_t)m * (2 * DINNER) + DINNER + c);
    yv.x *= zv.x / (1.f + __expf(-zv.x));
    yv.y *= zv.y / (1.f + __expf(-zv.y));
    yv.z *= zv.z / (1.f + __expf(-zv.z));
    yv.w *= zv.w / (1.f + __expf(-zv.w));
    *(float4*)(y + (size_t)m * DINNER + c) = yv;
}

// ---------------- host ------------------------------------------------------
static float* symaddr(const void* sym)
{
    void* p = nullptr;
    cudaGetSymbolAddress(&p, sym);
    return (float*)p;
}

extern "C" void kernel_launch(void* const* d_in, const int* in_sizes, int n_in,
                              void* d_out, int out_size)
{
    const float* x          = (const float*)d_in[0];
    const float* W_in       = (const float*)d_in[1];
    const float* W_x        = (const float*)d_in[2];
    const float* W_dt       = (const float*)d_in[3];
    const float* b_dt       = (const float*)d_in[4];
    const float* A_log_real = (const float*)d_in[5];
    const float* A_imag     = (const float*)d_in[6];
    const float* D_param    = (const float*)d_in[7];
    const float* W_out      = (const float*)d_in[8];
    const float* ln_g       = (const float*)d_in[9];
    const float* ln_b       = (const float*)d_in[10];
    float* out = (float*)d_out;

    float* p_xn   = symaddr(g_xn);
    float* p_xz   = symaddr(g_xz);
    float* p_xdbl = symaddr(g_xdbl);
    float* p_part = symaddr(g_part);
    float* p_dt   = symaddr(g_dt);
    float* p_dtT  = symaddr(g_dtT);
    float* p_xT   = symaddr(g_xT);
    float* p_y    = symaddr(g_y);

    // 1. LayerNorm
    ln_kernel<<<MM, 256>>>(x, ln_g, ln_b, p_xn);

    // 2. in-proj: xz = xn @ W_in^T   (M=4096, N=4096, K=1024)
    tmma<0><<<dim3(32, 32, 1), 256>>>(
        p_xn, DMODEL, W_in, DMODEL, p_xz, 2 * DINNER, DMODEL,
        nullptr, nullptr, 0, 0);

    // 3. x-proj: x_dbl = x_ssm @ W_x^T  (M=4096, N=128, K=2048) split-K x8
    tmma<0><<<dim3(1, 32, NSPLIT), 256>>>(
        p_xz, 2 * DINNER, W_x, DINNER, p_part, 128, DINNER / NSPLIT,
        nullptr, nullptr, 0, MM * 128);
    reduce_splitk<<<(MM * 128 + 255) / 256, 256>>>(p_part, p_xdbl, MM * 128);

    // 4. dt-proj + softplus: dt = softplus(dt_low @ W_dt^T + b_dt)  (K=64)
    tmma<1><<<dim3(16, 32, 1), 256>>>(
        p_xdbl, 128, W_dt, DTRANK, p_dt, DINNER, DTRANK,
        b_dt, nullptr, 0, 0);

    // 5. transpose dt, x_ssm to (b, e, t)
    transpose_dx<<<dim3(TT / 32, DINNER / 32, BB), dim3(32, 8)>>>(p_dt, p_xz, p_dtT, p_xT);

    // 6. selective scan
    scan_kernel<<<dim3(DINNER / 8, BB), 256>>>(p_dtT, p_xT, p_xdbl,
                                               A_log_real, A_imag, D_param, p_y);

    // 7. y *= silu(z)
    yz_kernel<<<(MM * DINNER / 4) / 256, 256>>>(p_y, p_xz);

    // 8. out-proj + residual: out = x + y @ W_out^T  (M=4096, N=1024, K=2048)
    tmma<2><<<dim3(8, 32, 1), 256>>>(
        p_y, DINNER, W_out, DINNER, out, DMODEL, DINNER,
        nullptr, x, DMODEL, 0);
}